// round 8
// baseline (speedup 1.0000x reference)
#include <cuda_runtime.h>
#include <cuda_bf16.h>
#include <cstdint>

// Involution2D on GB300 — round 8:
//   - g_x_hi/lo eliminated: GEMM kernels read x fp32 and split inline (LDG->STS)
//   - k_xi_mma: M=128 tile (512 thr, 16 warps) halves B (WiT) L2 traffic
//   - k_prepw: tiny weight-only prep (22 blocks)
//   - k_rw_mma: A chunks from x fp32, full-prefetch layout kept
//   - k_inv: unchanged (near its gather floor)

#define BB   4
#define HH_  128
#define WW_  128
#define CC   256
#define CR   64
#define KKG  144
#define FF   256
#define NPIX (BB*HH_*WW_)   // 65536

__device__ __align__(16) float g_w_buf[(size_t)NPIX * KKG];
__device__ __align__(16) float g_xi_buf[(size_t)NPIX * FF];
__device__ __align__(16) unsigned int g_wiT_hi[256 * 128];   // [f][c/2]
__device__ __align__(16) unsigned int g_wiT_lo[256 * 128];
__device__ __align__(16) unsigned int g_wrT_hi[64 * 128];    // [n][c/2]
__device__ __align__(16) unsigned int g_wrT_lo[64 * 128];
__device__ __align__(16) unsigned int g_wsT_hi[144 * 32];    // [f][k/2]
__device__ __align__(16) unsigned int g_wsT_lo[144 * 32];

#define SW(o) ((o) ^ (((o) >> 3) & 0x70))

__device__ __forceinline__ uint32_t smem_to_u32(const void* p) {
    uint32_t a;
    asm("{ .reg .u64 t; cvta.to.shared.u64 t, %1; cvt.u32.u64 %0, t; }"
        : "=r"(a) : "l"(p));
    return a;
}
__device__ __forceinline__ uint32_t bf16x2_rn(float lo, float hi) {
    uint32_t r;
    asm("cvt.rn.bf16x2.f32 %0, %1, %2;" : "=r"(r) : "f"(hi), "f"(lo));
    return r;
}
__device__ __forceinline__ void split2(float a, float b, uint32_t &hi, uint32_t &lo) {
    uint32_t ua = __float_as_uint(a), ub = __float_as_uint(b);
    hi = __byte_perm(ua, ub, 0x7632);
    lo = bf16x2_rn(a - __uint_as_float(ua & 0xFFFF0000u),
                   b - __uint_as_float(ub & 0xFFFF0000u));
}
__device__ __forceinline__ void cp_async16(uint32_t dst, const void* src) {
    asm volatile("{ .reg .u64 g; cvta.to.global.u64 g, %1;\n\t"
                 "cp.async.cg.shared.global [%0], [g], 16; }"
                 :: "r"(dst), "l"(src) : "memory");
}
__device__ __forceinline__ void cp_async16_z(uint32_t dst, const void* src, int sz) {
    asm volatile("{ .reg .u64 g; cvta.to.global.u64 g, %1;\n\t"
                 "cp.async.cg.shared.global [%0], [g], 16, %2; }"
                 :: "r"(dst), "l"(src), "r"(sz) : "memory");
}
#define CP_COMMIT() asm volatile("cp.async.commit_group;" ::: "memory")
#define CP_WAIT(n)  asm volatile("cp.async.wait_group %0;" :: "n"(n) : "memory")

__device__ __forceinline__ void ldsm4(uint32_t (&r)[4], const void* p) {
    uint32_t addr;
    asm("{ .reg .u64 t; cvta.to.shared.u64 t, %1; cvt.u32.u64 %0, t; }"
        : "=r"(addr) : "l"(p));
    asm volatile("ldmatrix.sync.aligned.m8n8.x4.shared.b16 {%0,%1,%2,%3}, [%4];"
                 : "=r"(r[0]), "=r"(r[1]), "=r"(r[2]), "=r"(r[3]) : "r"(addr));
}
__device__ __forceinline__ void mma16816(float (&d)[4], const uint32_t (&a)[4],
                                         uint32_t b0, uint32_t b1) {
    asm volatile(
        "mma.sync.aligned.m16n8k16.row.col.f32.bf16.bf16.f32 "
        "{%0,%1,%2,%3}, {%4,%5,%6,%7}, {%8,%9}, {%0,%1,%2,%3};"
        : "+f"(d[0]), "+f"(d[1]), "+f"(d[2]), "+f"(d[3])
        : "r"(a[0]), "r"(a[1]), "r"(a[2]), "r"(a[3]), "r"(b0), "r"(b1));
}

// ---------------- prep: weight transposes + hi/lo (22 blocks) ----------------
__global__ void __launch_bounds__(256)
k_prepw(const float* __restrict__ Wi, const float* __restrict__ Wr,
        const float* __restrict__ Ws)
{
    const int bid = blockIdx.x;
    const int t   = threadIdx.x;
    if (bid < 16) {
        const int idx = bid * 256 + t;
        for (int i = idx; i < 32768; i += 4096) {
            int f = i >> 7, cp = i & 127;
            uint32_t hi, lo;
            split2(Wi[(size_t)(2 * cp) * 256 + f],
                   Wi[(size_t)(2 * cp + 1) * 256 + f], hi, lo);
            g_wiT_hi[f * 128 + cp] = hi;
            g_wiT_lo[f * 128 + cp] = lo;
        }
    } else if (bid < 20) {
        const int idx = (bid - 16) * 256 + t;
        for (int i = idx; i < 8192; i += 1024) {
            int n = i >> 7, kp = i & 127;
            uint32_t hi, lo;
            split2(Wr[(2 * kp) * 64 + n], Wr[(2 * kp + 1) * 64 + n], hi, lo);
            g_wrT_hi[n * 128 + kp] = hi;
            g_wrT_lo[n * 128 + kp] = lo;
        }
    } else {
        const int idx = (bid - 20) * 256 + t;
        for (int i = idx; i < 4608; i += 512) {
            int f = i >> 5, kp = i & 31;
            uint32_t hi, lo;
            split2(Ws[(2 * kp) * 144 + f], Ws[(2 * kp + 1) * 144 + f], hi, lo);
            g_wsT_hi[f * 32 + kp] = hi;
            g_wsT_lo[f * 32 + kp] = lo;
        }
    }
}

// ---------------- kernel: xi = x @ Wi + bi, M=128, 512 threads ----------------
#define XG_A_HI 0
#define XG_A_LO 16384
#define XG_B_HI 32768
#define XG_B_LO 65536
#define XG_BUF  98304
#define XG_SMEM (2 * XG_BUF)   // 196608

// issue B chunk kb into buf via cp.async (one commit group by caller)
__device__ __forceinline__ void xi_issue_B(uint32_t sb, int buf, int kb, int t)
{
    const uint32_t base = sb + buf * XG_BUF;
    const uint4* gbh = (const uint4*)g_wiT_hi;
    const uint4* gbl = (const uint4*)g_wiT_lo;
    #pragma unroll
    for (int it = 0; it < 4; ++it) {          // 256 rows x 8 x 16B
        int gi = t + it * 512;
        int f = gi >> 3, c = gi & 7;
        int src = f * 32 + kb * 8 + c;
        uint32_t d = SW(f * 128 + c * 16);
        cp_async16(base + XG_B_HI + d, gbh + src);
        cp_async16(base + XG_B_LO + d, gbl + src);
    }
}
// A fp32 chunk kb -> registers (4 x float4 per thread)
__device__ __forceinline__ void xi_ldg_A(const float* __restrict__ x, int p0,
                                         int kb, int t, float4 (&rA)[4])
{
    const float4* xs = (const float4*)x;
    #pragma unroll
    for (int it = 0; it < 4; ++it) {
        int gi = t + it * 512;
        int row = gi >> 4, c4 = gi & 15;      // 128 rows x 16 float4
        rA[it] = xs[(size_t)(p0 + row) * 64 + kb * 16 + c4];
    }
}
// convert + STS A chunk from registers into buf
__device__ __forceinline__ void xi_sts_A(char* smc, int buf, int t,
                                         const float4 (&rA)[4])
{
    char* base = smc + buf * XG_BUF;
    #pragma unroll
    for (int it = 0; it < 4; ++it) {
        int gi = t + it * 512;
        int row = gi >> 4, c4 = gi & 15;
        uint32_t h0, l0, h1, l1;
        split2(rA[it].x, rA[it].y, h0, l0);
        split2(rA[it].z, rA[it].w, h1, l1);
        uint32_t d = SW(row * 128 + c4 * 8);
        *(uint2*)(base + XG_A_HI + d) = make_uint2(h0, h1);
        *(uint2*)(base + XG_A_LO + d) = make_uint2(l0, l1);
    }
}

__global__ void __launch_bounds__(512, 1)
k_xi_mma(const float* __restrict__ x, const float* __restrict__ bi)
{
    extern __shared__ char smc[];
    const uint32_t sb = smem_to_u32(smc);
    const int t    = threadIdx.x;
    const int wid  = t >> 5;
    const int lane = t & 31;
    const int p0   = blockIdx.x * 128;
    const int wm   = wid >> 2;           // 0..3
    const int wn   = wid & 3;            // 0..3

    float4 rA[4];

    // prologue: A0,A1 -> smem; B0,B1 in flight; A2 in regs
    xi_ldg_A(x, p0, 0, t, rA);
    xi_issue_B(sb, 0, 0, t); CP_COMMIT();
    xi_sts_A(smc, 0, t, rA);
    xi_ldg_A(x, p0, 1, t, rA);
    xi_issue_B(sb, 1, 1, t); CP_COMMIT();
    xi_sts_A(smc, 1, t, rA);
    xi_ldg_A(x, p0, 2, t, rA);

    float acc[2][8][4];
    #pragma unroll
    for (int i = 0; i < 2; ++i)
        #pragma unroll
        for (int j = 0; j < 8; ++j)
            #pragma unroll
            for (int q = 0; q < 4; ++q) acc[i][j][q] = 0.f;

    const int lr   = lane & 15;
    const int lk   = (lane >> 4) * 16;
    const int arow = wm * 32 + lr;
    const int brow = wn * 64 + lr;

    for (int kb = 0; kb < 4; ++kb) {
        if (kb < 3) CP_WAIT(1); else CP_WAIT(0);
        __syncthreads();
        char* base = smc + (kb & 1) * XG_BUF;
        #pragma unroll
        for (int k16 = 0; k16 < 4; ++k16) {
            const int ko = k16 * 32 + lk;
            uint32_t ah[2][4], al[2][4];
            #pragma unroll
            for (int i = 0; i < 2; ++i) {
                ldsm4(ah[i], base + XG_A_HI + SW((arow + i * 16) * 128 + ko));
                ldsm4(al[i], base + XG_A_LO + SW((arow + i * 16) * 128 + ko));
            }
            #pragma unroll
            for (int j = 0; j < 4; ++j) {
                uint32_t bh[4], bl[4];
                ldsm4(bh, base + XG_B_HI + SW((brow + j * 16) * 128 + ko));
                ldsm4(bl, base + XG_B_LO + SW((brow + j * 16) * 128 + ko));
                #pragma unroll
                for (int i = 0; i < 2; ++i) {
                    mma16816(acc[i][2*j],   ah[i], bh[0], bh[2]);
                    mma16816(acc[i][2*j+1], ah[i], bh[1], bh[3]);
                    mma16816(acc[i][2*j],   al[i], bh[0], bh[2]);
                    mma16816(acc[i][2*j+1], al[i], bh[1], bh[3]);
                    mma16816(acc[i][2*j],   ah[i], bl[0], bl[2]);
                    mma16816(acc[i][2*j+1], ah[i], bl[1], bl[3]);
                }
            }
        }
        __syncthreads();
        if (kb + 2 < 4) {
            xi_sts_A(smc, kb & 1, t, rA);          // rA holds chunk kb+2
            xi_issue_B(sb, kb & 1, kb + 2, t); CP_COMMIT();
            if (kb + 3 < 4) xi_ldg_A(x, p0, kb + 3, t, rA);
        }
    }

    const int g  = lane >> 2;
    const int t2 = (lane & 3) * 2;
    #pragma unroll
    for (int i = 0; i < 2; ++i) {
        const int m = p0 + wm * 32 + i * 16 + g;
        #pragma unroll
        for (int j = 0; j < 8; ++j) {
            const int n = wn * 64 + j * 8 + t2;
            float b0 = bi[n], b1 = bi[n + 1];
            *(float2*)&g_xi_buf[(size_t)m * 256 + n] =
                make_float2(acc[i][j][0] + b0, acc[i][j][1] + b1);
            *(float2*)&g_xi_buf[(size_t)(m + 8) * 256 + n] =
                make_float2(acc[i][j][2] + b0, acc[i][j][3] + b1);
        }
    }
}

// ---------------- kernel: r+w fused; A from x fp32, weights cp.async ----------------
#define RW_WS_HI 0
#define RW_WS_LO 18432
#define RW_SC    36864
#define RW_SH    37120
#define RW_A_HI  37376     // 4 chunks x 8192
#define RW_A_LO  70144
#define RW_B_HI  102912
#define RW_B_LO  135680
#define RW_R_HI  168448
#define RW_R_LO  176640
#define RW_SMEM  184832

__global__ void __launch_bounds__(256, 1)
k_rw_mma(const float* __restrict__ x,
         const float* __restrict__ br,   const float* __restrict__ gamma,
         const float* __restrict__ beta, const float* __restrict__ mean,
         const float* __restrict__ var,  const float* __restrict__ bs)
{
    extern __shared__ char smc[];
    const uint32_t sb = smem_to_u32(smc);
    const int t    = threadIdx.x;
    const int wid  = t >> 5;
    const int lane = t & 31;
    const int p0   = blockIdx.x * 64;
    const int wm   = wid >> 2;
    const int wn   = wid & 3;

    // A: all 4 chunks of x fp32 -> registers (issue early)
    float4 rx[16];
    {
        const float4* xs = (const float4*)x;
        #pragma unroll
        for (int kb = 0; kb < 4; ++kb)
            #pragma unroll
            for (int it = 0; it < 4; ++it) {
                int gi = t + it * 256;
                int row = gi >> 4, c4 = gi & 15;   // 64 rows x 16 float4
                rx[kb * 4 + it] = xs[(size_t)(p0 + row) * 64 + kb * 16 + c4];
            }
    }
    // group 0: resident WsT hi/lo
    {
        const uint4* sh = (const uint4*)g_wsT_hi;
        const uint4* sl = (const uint4*)g_wsT_lo;
        for (int i = t; i < 1152; i += 256) {
            int f = i >> 3, c = i & 7;
            uint32_t d = SW(f * 128 + c * 16);
            cp_async16(sb + RW_WS_HI + d, sh + i);
            cp_async16(sb + RW_WS_LO + d, sl + i);
        }
    }
    CP_COMMIT();
    // groups 1..4: WrT B chunks
    {
        const uint4* grh = (const uint4*)g_wrT_hi;
        const uint4* grl = (const uint4*)g_wrT_lo;
        #pragma unroll
        for (int kb = 0; kb < 4; ++kb) {
            #pragma unroll
            for (int it = 0; it < 2; ++it) {      // B: 64 rows x 8 x 16B
                int gi = t + it * 256;
                int n = gi >> 3, c = gi & 7;
                int src = n * 32 + kb * 8 + c;
                uint32_t d = kb * 8192 + SW(n * 128 + c * 16);
                cp_async16(sb + RW_B_HI + d, grh + src);
                cp_async16(sb + RW_B_LO + d, grl + src);
            }
            CP_COMMIT();
        }
    }
    // convert + STS all A chunks
    #pragma unroll
    for (int kb = 0; kb < 4; ++kb)
        #pragma unroll
        for (int it = 0; it < 4; ++it) {
            int gi = t + it * 256;
            int row = gi >> 4, c4 = gi & 15;
            float4 v = rx[kb * 4 + it];
            uint32_t h0, l0, h1, l1;
            split2(v.x, v.y, h0, l0);
            split2(v.z, v.w, h1, l1);
            uint32_t d = kb * 8192 + SW(row * 128 + c4 * 8);
            *(uint2*)(smc + RW_A_HI + d) = make_uint2(h0, h1);
            *(uint2*)(smc + RW_A_LO + d) = make_uint2(l0, l1);
        }
    // BN constants
    if (t < 64) {
        float s = gamma[t] * rsqrtf(var[t] + 1e-3f);
        *(float*)(smc + RW_SC + t * 4) = s;
        *(float*)(smc + RW_SH + t * 4) = (br[t] - mean[t]) * s + beta[t];
    }

    const int lr    = lane & 15;
    const int lk    = (lane >> 4) * 16;
    const int arow  = wm * 32 + lr;
    const int brow1 = wn * 16 + lr;

    // ---- GEMM1: x @ Wr  (N=64, K=256) ----
    float acc1[2][2][4];
    #pragma unroll
    for (int i = 0; i < 2; ++i)
        #pragma unroll
        for (int j = 0; j < 2; ++j)
            #pragma unroll
            for (int q = 0; q < 4; ++q) acc1[i][j][q] = 0.f;

    #pragma unroll
    for (int kb = 0; kb < 4; ++kb) {
        if      (kb == 0) CP_WAIT(3);
        else if (kb == 1) CP_WAIT(2);
        else if (kb == 2) CP_WAIT(1);
        else              CP_WAIT(0);
        __syncthreads();
        char* abase  = smc + RW_A_HI + kb * 8192;
        char* albase = smc + RW_A_LO + kb * 8192;
        char* bbase  = smc + RW_B_HI + kb * 8192;
        char* blbase = smc + RW_B_LO + kb * 8192;
        #pragma unroll
        for (int k16 = 0; k16 < 4; ++k16) {
            const int ko = k16 * 32 + lk;
            uint32_t ah[2][4], al[2][4], bh[4], bl[4];
            #pragma unroll
            for (int i = 0; i < 2; ++i) {
                ldsm4(ah[i], abase  + SW((arow + i * 16) * 128 + ko));
                ldsm4(al[i], albase + SW((arow + i * 16) * 128 + ko));
            }
            ldsm4(bh, bbase  + SW(brow1 * 128 + ko));
            ldsm4(bl, blbase + SW(brow1 * 128 + ko));
            #pragma unroll
            for (int i = 0; i < 2; ++i) {
                mma16816(acc1[i][0], ah[i], bh[0], bh[2]);
                mma16816(acc1[i][1], ah[i], bh[1], bh[3]);
                mma16816(acc1[i][0], al[i], bh[0], bh[2]);
                mma16816(acc1[i][1], al[i], bh[1], bh[3]);
                mma16816(acc1[i][0], ah[i], bl[0], bl[2]);
                mma16816(acc1[i][1], ah[i], bl[1], bl[3]);
            }
        }
    }

    // ---- epilogue 1: BN + relu, split r -> smem hi/lo ----
    {
        const int g  = lane >> 2;
        const int t2 = (lane & 3) * 2;
        #pragma unroll
        for (int i = 0; i < 2; ++i) {
            #pragma unroll
            for (int n8 = 0; n8 < 2; ++n8) {
                const int n0 = wn * 16 + n8 * 8 + t2;
                const float s0 = *(float*)(smc + RW_SC + n0 * 4);
                const float s1 = *(float*)(smc + RW_SC + (n0 + 1) * 4);
                const float h0 = *(float*)(smc + RW_SH + n0 * 4);
                const float h1 = *(float*)(smc + RW_SH + (n0 + 1) * 4);
                #pragma unroll
                for (int half = 0; half < 2; ++half) {
                    const int m = wm * 32 + i * 16 + g + half * 8;
                    float r0 = fmaxf(fmaf(acc1[i][n8][half * 2],     s0, h0), 0.f);
                    float r1 = fmaxf(fmaf(acc1[i][n8][half * 2 + 1], s1, h1), 0.f);
                    uint32_t hi, lo;
                    split2(r0, r1, hi, lo);
                    uint32_t d = SW(m * 128 + n0 * 2);
                    *(uint32_t*)(smc + RW_R_HI + d) = hi;
                    *(uint32_t*)(smc + RW_R_LO + d) = lo;
                }
            }
        }
    }
    __syncthreads();

    // ---- GEMM2: w = r @ Ws + bs  (N=144, K=64) ----
    const int nblk = (wn == 3) ? 3 : 2;
    int blkid[3] = {wn, wn + 4, 8};
    float acc2[3][2][2][4];
    #pragma unroll
    for (int b = 0; b < 3; ++b)
        #pragma unroll
        for (int i = 0; i < 2; ++i)
            #pragma unroll
            for (int j = 0; j < 2; ++j)
                #pragma unroll
                for (int q = 0; q < 4; ++q) acc2[b][i][j][q] = 0.f;

    #pragma unroll
    for (int k16 = 0; k16 < 4; ++k16) {
        const int ko = k16 * 32 + lk;
        uint32_t ah[2][4], al[2][4];
        #pragma unroll
        for (int i = 0; i < 2; ++i) {
            ldsm4(ah[i], smc + RW_R_HI + SW((arow + i * 16) * 128 + ko));
            ldsm4(al[i], smc + RW_R_LO + SW((arow + i * 16) * 128 + ko));
        }
        for (int b = 0; b < nblk; ++b) {
            const int brow = blkid[b] * 16 + lr;
            uint32_t bh[4], bl[4];
            ldsm4(bh, smc + RW_WS_HI + SW(brow * 128 + ko));
            ldsm4(bl, smc + RW_WS_LO + SW(brow * 128 + ko));
            #pragma unroll
            for (int i = 0; i < 2; ++i) {
                mma16816(acc2[b][i][0], ah[i], bh[0], bh[2]);
                mma16816(acc2[b][i][1], ah[i], bh[1], bh[3]);
                mma16816(acc2[b][i][0], al[i], bh[0], bh[2]);
                mma16816(acc2[b][i][1], al[i], bh[1], bh[3]);
                mma16816(acc2[b][i][0], ah[i], bl[0], bl[2]);
                mma16816(acc2[b][i][1], ah[i], bl[1], bl[3]);
            }
        }
    }

    // ---- epilogue 2: w -> g_w_buf (+bs) ----
    {
        const int g  = lane >> 2;
        const int t2 = (lane & 3) * 2;
        for (int b = 0; b < nblk; ++b) {
            #pragma unroll
            for (int j = 0; j < 2; ++j) {
                const int n = blkid[b] * 16 + j * 8 + t2;
                const float b0 = bs[n], b1 = bs[n + 1];
                #pragma unroll
                for (int i = 0; i < 2; ++i) {
                    const int m = p0 + wm * 32 + i * 16 + g;
                    *(float2*)&g_w_buf[(size_t)m * 144 + n] =
                        make_float2(acc2[b][i][j][0] + b0, acc2[b][i][j][1] + b1);
                    *(float2*)&g_w_buf[(size_t)(m + 8) * 144 + n] =
                        make_float2(acc2[b][i][j][2] + b0, acc2[b][i][j][3] + b1);
                }
            }
        }
    }
}

// ---------------- kernel: involution gather/reduce (round-7 proven) ----------------
#define INV_SMEM_FLOATS (3*18*256 + 16*144)

__global__ void __launch_bounds__(256)
k_inv(float* __restrict__ out)
{
    extern __shared__ float sm2[];
    float* xis = sm2;                       // [54][256]
    float* wsm = sm2 + 13824;               // [16][144]
    const uint32_t sb = smem_to_u32(sm2);

    const int t   = threadIdx.x;
    const int seg = blockIdx.x & 7;
    const int h   = (blockIdx.x >> 3) & 127;
    const int b   = blockIdx.x >> 10;
    const int w0  = seg * 16;
    const size_t prow = ((size_t)b * 128 + h) * 128;

    {
        const uint4* src = (const uint4*)(g_w_buf + (prow + w0) * 144);
        for (int i = t; i < 576; i += 256)
            cp_async16(sb + 55296 + i * 16, src + i);
    }
    for (int i = t; i < 3456; i += 256) {
        int pos = i >> 6, c4 = i & 63;
        int rr = pos / 18, cc = pos - rr * 18;
        int hhp = h - 1 + rr, wwp = w0 - 1 + cc;
        bool ok = ((unsigned)hhp < 128u) && ((unsigned)wwp < 128u);
        const uint4* s = ok
            ? (const uint4*)(g_xi_buf + (((size_t)b * 128 + hhp) * 128 + wwp) * 256) + c4
            : (const uint4*)g_xi_buf;
        cp_async16_z(sb + (uint32_t)(pos * 1024 + c4 * 16), s, ok ? 16 : 0);
    }
    CP_COMMIT();
    CP_WAIT(0);
    __syncthreads();

    const int o  = t;
    const int g  = o >> 4;
    const int fb = g * 144 + (o & 15) * 9;
    int off[9];
    #pragma unroll
    for (int kk = 0; kk < 9; kk++) {
        int flat = fb + kk;
        int kpos = flat >> 8;
        int c    = flat & 255;
        int di   = kpos / 3, dj = kpos - di * 3;
        off[kk]  = (di * 18 + dj) * 256 + c;
    }

    for (int px = 0; px < 16; px++) {
        const float* wp = &wsm[px * 144 + g * 9];
        const float* xb = &xis[px * 256];
        float acc = 0.f;
        #pragma unroll
        for (int kk = 0; kk < 9; kk++)
            acc = fmaf(wp[kk], xb[off[kk]], acc);
        out[(prow + w0 + px) * 256 + o] = acc;
    }
}

// ---------------- launch ----------------
extern "C" void kernel_launch(void* const* d_in, const int* in_sizes, int n_in,
                              void* d_out, int out_size)
{
    const float* x     = (const float*)d_in[0];
    const float* Wr    = (const float*)d_in[1];
    const float* br    = (const float*)d_in[2];
    const float* gamma = (const float*)d_in[3];
    const float* beta  = (const float*)d_in[4];
    const float* mean  = (const float*)d_in[5];
    const float* var   = (const float*)d_in[6];
    const float* Ws    = (const float*)d_in[7];
    const float* bs    = (const float*)d_in[8];
    const float* Wi    = (const float*)d_in[9];
    const float* bi    = (const float*)d_in[10];
    float* out = (float*)d_out;
    (void)in_sizes; (void)n_in; (void)out_size;

    const int smemX  = XG_SMEM;                                 // 196,608
    const int smemRW = RW_SMEM;                                 // 184,832
    const int smem2  = INV_SMEM_FLOATS * (int)sizeof(float);    // 64,512
    cudaFuncSetAttribute(k_xi_mma, cudaFuncAttributeMaxDynamicSharedMemorySize, smemX);
    cudaFuncSetAttribute(k_rw_mma, cudaFuncAttributeMaxDynamicSharedMemorySize, smemRW);
    cudaFuncSetAttribute(k_inv,    cudaFuncAttributeMaxDynamicSharedMemorySize, smem2);

    k_prepw  <<<22,         256>>>(Wi, Wr, Ws);
    k_xi_mma <<<NPIX / 128, 512, smemX>>>(x, bi);
    k_rw_mma <<<NPIX / 64,  256, smemRW>>>(x, br, gamma, beta, mean, var, bs);
    k_inv    <<<NPIX / 16,  256, smem2>>>(out);
}